// round 1
// baseline (speedup 1.0000x reference)
#include <cuda_runtime.h>

// Problem: out[b,g,k] = sum_d (h[b,g,d]/||h[b,g,:]||) * (w[g,d,k]/||w[g,:,k]||)
// B=512, G=100, D=768, K=100. All fp32.
// Strategy: precompute inverse norms (2 memory-bound kernels), then one
// fp32 tiled batched GEMM scaling in the epilogue.

#define B_ 512
#define G_ 100
#define D_ 768
#define K_ 100

#define BM 128
#define BN 104   // padded K tile (guard k < 100)
#define BK 16
#define NIT (D_ / BK)   // 48

// scratch (allocation-free rule: device globals)
__device__ float g_inv_h[B_ * G_];   // [b*G + g]
__device__ float g_inv_w[G_ * K_];   // [g*K + k]

// ---------------------------------------------------------------------------
// Kernel 1: inv_h[row] = 1 / max(||h_row||, eps), one warp per (b,g) row.
// 51200 rows, 768 floats each, fully coalesced float4 reads.
// ---------------------------------------------------------------------------
__global__ void norm_h_kernel(const float* __restrict__ h) {
    int warp = (blockIdx.x * blockDim.x + threadIdx.x) >> 5;
    int lane = threadIdx.x & 31;
    if (warp >= B_ * G_) return;
    const float4* p = reinterpret_cast<const float4*>(h + (size_t)warp * D_);
    float s = 0.f;
#pragma unroll
    for (int t = 0; t < 6; t++) {           // 6*32*4 = 768
        float4 v = p[lane + 32 * t];
        s += v.x * v.x + v.y * v.y + v.z * v.z + v.w * v.w;
    }
#pragma unroll
    for (int o = 16; o; o >>= 1) s += __shfl_xor_sync(0xffffffffu, s, o);
    if (lane == 0) g_inv_h[warp] = 1.0f / fmaxf(sqrtf(s), 1e-12f);
}

// ---------------------------------------------------------------------------
// Kernel 2: inv_w[g,k] = 1 / max(||w[g,:,k]||, eps).
// One block per g; 512 threads = 4 d-chunks x 128 k-slots; smem combine.
// ---------------------------------------------------------------------------
__global__ void norm_w_kernel(const float* __restrict__ w) {
    __shared__ float partial[4][128];
    int g = blockIdx.x;
    int k = threadIdx.x & 127;
    int c = threadIdx.x >> 7;                      // 0..3, 192 d each
    float s = 0.f;
    if (k < K_) {
        const float* base = w + (size_t)g * D_ * K_ + (size_t)c * 192 * K_ + k;
#pragma unroll 8
        for (int d = 0; d < 192; d++) {
            float v = base[(size_t)d * K_];
            s += v * v;
        }
    }
    partial[c][k] = s;
    __syncthreads();
    if (c == 0 && k < K_) {
        float t = partial[0][k] + partial[1][k] + partial[2][k] + partial[3][k];
        g_inv_w[g * K_ + k] = 1.0f / fmaxf(sqrtf(t), 1e-12f);
    }
}

// ---------------------------------------------------------------------------
// Kernel 3: batched GEMM with epilogue scaling.
// Block = (m-tile of 128 rows of b) x (all 100 k) for one group g.
// 256 threads, per-thread 4 rows x 13 cols of fp32 accumulators.
// Register-prefetch of next global tile overlaps smem compute.
// ---------------------------------------------------------------------------
__global__ __launch_bounds__(256, 2)
void gemm_kernel(const float* __restrict__ h, const float* __restrict__ w,
                 float* __restrict__ out) {
    __shared__ float As[BK][BM];   // A transposed: As[kk][row]
    __shared__ float Bs[BK][BN];   // Bs[kk][col], BN=104 pad

    const int g   = blockIdx.y;
    const int m0  = blockIdx.x * BM;
    const int tid = threadIdx.x;

    // --- A tile load mapping: 128 rows x 16 d = 512 float4; 2 per thread ---
    // idx -> row r = idx>>2, quad q = idx&3 (d offset q*4)
    const int ra0 = (tid)       >> 2, qa0 = (tid)       & 3;
    const int ra1 = (tid + 256) >> 2, qa1 = (tid + 256) & 3;
    const float* pAg0 = h + ((size_t)(m0 + ra0) * G_ + g) * D_ + qa0 * 4;
    const float* pAg1 = h + ((size_t)(m0 + ra1) * G_ + g) * D_ + qa1 * 4;

    // --- B tile load mapping: 16 rows x 100 floats = 400 float4 ---
    // p -> j = p/25 (d row), c4 = p%25 (k = c4*4)
    const int p0 = tid;          const bool v0 = (p0 < 400);
    const int p1 = tid + 256;    const bool v1 = (p1 < 400);
    const int jb0 = p0 / 25, cb0 = p0 % 25;
    const int jb1 = p1 / 25, cb1 = p1 % 25;
    const float* pBg0 = w + ((size_t)g * D_ + jb0) * K_ + cb0 * 4;
    const float* pBg1 = w + ((size_t)g * D_ + jb1) * K_ + cb1 * 4;

    const int tx = tid & 7;     // col group: cols tx + 8*j, j<13
    const int tm = tid >> 3;    // row group: rows tm*4 .. tm*4+3

    float acc[4][13];
#pragma unroll
    for (int i = 0; i < 4; i++)
#pragma unroll
        for (int j = 0; j < 13; j++) acc[i][j] = 0.f;

    // prefetch registers
    float4 fa0, fa1, fb0, fb1;

    // ---- load tile 0 ----
    fa0 = *reinterpret_cast<const float4*>(pAg0);
    fa1 = *reinterpret_cast<const float4*>(pAg1);
    fb0 = v0 ? *reinterpret_cast<const float4*>(pBg0) : make_float4(0, 0, 0, 0);
    fb1 = v1 ? *reinterpret_cast<const float4*>(pBg1) : make_float4(0, 0, 0, 0);

    // store tile 0 to smem
    As[qa0 * 4 + 0][ra0] = fa0.x; As[qa0 * 4 + 1][ra0] = fa0.y;
    As[qa0 * 4 + 2][ra0] = fa0.z; As[qa0 * 4 + 3][ra0] = fa0.w;
    As[qa1 * 4 + 0][ra1] = fa1.x; As[qa1 * 4 + 1][ra1] = fa1.y;
    As[qa1 * 4 + 2][ra1] = fa1.z; As[qa1 * 4 + 3][ra1] = fa1.w;
    if (v0) *reinterpret_cast<float4*>(&Bs[jb0][cb0 * 4]) = fb0;
    if (v1) *reinterpret_cast<float4*>(&Bs[jb1][cb1 * 4]) = fb1;
    __syncthreads();

    for (int t = 0; t < NIT; t++) {
        // prefetch next tile from global into registers
        if (t + 1 < NIT) {
            const int d0 = (t + 1) * BK;
            fa0 = *reinterpret_cast<const float4*>(pAg0 + d0);
            fa1 = *reinterpret_cast<const float4*>(pAg1 + d0);
            fb0 = v0 ? *reinterpret_cast<const float4*>(pBg0 + (size_t)d0 * K_)
                     : make_float4(0, 0, 0, 0);
            fb1 = v1 ? *reinterpret_cast<const float4*>(pBg1 + (size_t)d0 * K_)
                     : make_float4(0, 0, 0, 0);
        }

        // compute on current smem tile
#pragma unroll
        for (int kk = 0; kk < BK; kk++) {
            float4 a = *reinterpret_cast<const float4*>(&As[kk][tm * 4]);
            float b[13];
#pragma unroll
            for (int j = 0; j < 13; j++) b[j] = Bs[kk][tx + 8 * j];
#pragma unroll
            for (int j = 0; j < 13; j++) {
                acc[0][j] += a.x * b[j];
                acc[1][j] += a.y * b[j];
                acc[2][j] += a.z * b[j];
                acc[3][j] += a.w * b[j];
            }
        }
        __syncthreads();

        if (t + 1 < NIT) {
            As[qa0 * 4 + 0][ra0] = fa0.x; As[qa0 * 4 + 1][ra0] = fa0.y;
            As[qa0 * 4 + 2][ra0] = fa0.z; As[qa0 * 4 + 3][ra0] = fa0.w;
            As[qa1 * 4 + 0][ra1] = fa1.x; As[qa1 * 4 + 1][ra1] = fa1.y;
            As[qa1 * 4 + 2][ra1] = fa1.z; As[qa1 * 4 + 3][ra1] = fa1.w;
            if (v0) *reinterpret_cast<float4*>(&Bs[jb0][cb0 * 4]) = fb0;
            if (v1) *reinterpret_cast<float4*>(&Bs[jb1][cb1 * 4]) = fb1;
            __syncthreads();
        }
    }

    // ---- epilogue: scale by inv norms, store ----
    float invh[4];
#pragma unroll
    for (int i = 0; i < 4; i++)
        invh[i] = g_inv_h[(size_t)(m0 + tm * 4 + i) * G_ + g];

#pragma unroll
    for (int j = 0; j < 13; j++) {
        int c = tx + 8 * j;
        if (c < K_) {
            float invw = g_inv_w[g * K_ + c];
#pragma unroll
            for (int i = 0; i < 4; i++) {
                int b = m0 + tm * 4 + i;
                out[((size_t)b * G_ + g) * K_ + c] = acc[i][j] * invh[i] * invw;
            }
        }
    }
}

// ---------------------------------------------------------------------------
extern "C" void kernel_launch(void* const* d_in, const int* in_sizes, int n_in,
                              void* d_out, int out_size) {
    const float* h = (const float*)d_in[0];   // [512,100,768]
    const float* w = (const float*)d_in[1];   // [100,768,100]
    float* out = (float*)d_out;               // [512,100,100]
    (void)in_sizes; (void)n_in; (void)out_size;

    norm_h_kernel<<<(B_ * G_) / 8, 256>>>(h);         // 1 warp per row
    norm_w_kernel<<<G_, 512>>>(w);
    dim3 grid(B_ / BM, G_);
    gemm_kernel<<<grid, 256>>>(h, w, out);
}

// round 2
// speedup vs baseline: 1.1502x; 1.1502x over previous
#include <cuda_runtime.h>
#include <cuda_bf16.h>
#include <cstdint>

// out[b,g,k] = sum_d (h[b,g,d]/||h[b,g,:]||) * (w[g,d,k]/||w[g,:,k]||)
// B=512, G=100, D=768, K=100.
// Strategy: bf16 two-term split (hi+lo) tensor-core GEMM, fp32 accumulate.
//   x*y ~= xh*yh + xh*yl + xl*yh   (error ~2^-18)
// W is pre-normalized/split/transposed to [G][128][768] bf16 scratch.
// H is normalized+split on the fly inside the GEMM (invh precomputed).

#define B_ 512
#define G_ 100
#define D_ 768
#define K_ 100
#define KP 128          // padded K (N dim of GEMM)
#define BKC 64          // k-chunk
#define NCHUNK (D_ / BKC)   // 12
#define LDA 72          // padded smem stride (bf16 elems) -> conflict-free frags

// ---------------- device scratch (allocation-free rule) ----------------
__device__ float g_inv_h[B_ * G_];              // [b*G+g]
__device__ float g_inv_w[G_ * K_];              // [g*K+k]
__device__ __nv_bfloat16 g_wt_hi[(size_t)G_ * KP * D_];  // [g][k][d], 39.3MB
__device__ __nv_bfloat16 g_wt_lo[(size_t)G_ * KP * D_];

// ---------------------------------------------------------------------------
// inv_h: one warp per (b,g) row. 157MB read, at HBM roofline.
// ---------------------------------------------------------------------------
__global__ void norm_h_kernel(const float* __restrict__ h) {
    int warp = (blockIdx.x * blockDim.x + threadIdx.x) >> 5;
    int lane = threadIdx.x & 31;
    if (warp >= B_ * G_) return;
    const float4* p = reinterpret_cast<const float4*>(h + (size_t)warp * D_);
    float s = 0.f;
#pragma unroll
    for (int t = 0; t < 6; t++) {
        float4 v = p[lane + 32 * t];
        s += v.x * v.x + v.y * v.y + v.z * v.z + v.w * v.w;
    }
#pragma unroll
    for (int o = 16; o; o >>= 1) s += __shfl_xor_sync(0xffffffffu, s, o);
    if (lane == 0) g_inv_h[warp] = 1.0f / fmaxf(sqrtf(s), 1e-12f);
}

// ---------------------------------------------------------------------------
// inv_w[g,k] = 1/max(||w[g,:,k]||, eps). One block per g.
// ---------------------------------------------------------------------------
__global__ void norm_w_kernel(const float* __restrict__ w) {
    __shared__ float partial[4][128];
    int g = blockIdx.x;
    int k = threadIdx.x & 127;
    int c = threadIdx.x >> 7;
    float s = 0.f;
    if (k < K_) {
        const float* base = w + (size_t)g * D_ * K_ + (size_t)c * 192 * K_ + k;
#pragma unroll 8
        for (int d = 0; d < 192; d++) {
            float v = base[(size_t)d * K_];
            s += v * v;
        }
    }
    partial[c][k] = s;
    __syncthreads();
    if (c == 0 && k < K_) {
        float t = partial[0][k] + partial[1][k] + partial[2][k] + partial[3][k];
        g_inv_w[g * K_ + k] = 1.0f / fmaxf(sqrtf(t), 1e-12f);
    }
}

// ---------------------------------------------------------------------------
// split_w: normalize, split to bf16 hi/lo, transpose to [g][k][d].
// grid (12 d-chunks, 100 g), 256 threads. k>=100 rows zero-filled.
// ---------------------------------------------------------------------------
__global__ void split_w_kernel(const float* __restrict__ w) {
    __shared__ float ws[64][104];   // [dd][k], padded
    const int dc = blockIdx.x;      // 0..11
    const int g  = blockIdx.y;
    const int tid = threadIdx.x;

    // load 64 x 100 fp32 tile (coalesced along k)
    const float* src = w + (size_t)g * D_ * K_ + (size_t)dc * 64 * K_;
#pragma unroll
    for (int i = 0; i < 25; i++) {
        int idx = tid + 256 * i;   // 6400 total
        int dd = idx / K_;
        int kk = idx % K_;
        ws[dd][kk] = src[idx];
    }
    __syncthreads();

    // each thread: one k (t>>1), 32 d's; write hi/lo bf16 contiguous
    const int k  = tid >> 1;
    const int d0 = (tid & 1) * 32;
    float invw = (k < K_) ? g_inv_w[g * K_ + k] : 0.f;

    __nv_bfloat16 hb[32], lb[32];
#pragma unroll
    for (int j = 0; j < 32; j++) {
        float x = (k < K_) ? ws[d0 + j][k] * invw : 0.f;
        __nv_bfloat16 hi = __float2bfloat16(x);
        hb[j] = hi;
        lb[j] = __float2bfloat16(x - __bfloat162float(hi));
    }
    size_t base = ((size_t)g * KP + k) * D_ + (size_t)dc * 64 + d0;
    uint4* dst_h = reinterpret_cast<uint4*>(g_wt_hi + base);
    uint4* dst_l = reinterpret_cast<uint4*>(g_wt_lo + base);
#pragma unroll
    for (int q = 0; q < 4; q++) {
        uint4 vh, vl;
        const uint32_t* ph = reinterpret_cast<const uint32_t*>(hb + q * 8);
        const uint32_t* pl = reinterpret_cast<const uint32_t*>(lb + q * 8);
        vh.x = ph[0]; vh.y = ph[1]; vh.z = ph[2]; vh.w = ph[3];
        vl.x = pl[0]; vl.y = pl[1]; vl.z = pl[2]; vl.w = pl[3];
        dst_h[q] = vh;
        dst_l[q] = vl;
    }
}

// ---------------------------------------------------------------------------
// GEMM: per (g, m-tile of 128): C[128,128] = An . Wn^T over D=768.
// bf16 mma.sync m16n8k16, fp32 acc, 3-product split.
// 8 warps: mw = warp&3 (32 rows), nw = warp>>2 (64 cols).
// ---------------------------------------------------------------------------
#define MMA_BF16(d, a, b0, b1)                                              \
    asm volatile(                                                           \
        "mma.sync.aligned.m16n8k16.row.col.f32.bf16.bf16.f32 "              \
        "{%0,%1,%2,%3}, {%4,%5,%6,%7}, {%8,%9}, {%0,%1,%2,%3};"             \
        : "+f"(d[0]), "+f"(d[1]), "+f"(d[2]), "+f"(d[3])                    \
        : "r"(a[0]), "r"(a[1]), "r"(a[2]), "r"(a[3]), "r"(b0), "r"(b1))

__global__ __launch_bounds__(256, 2)
void gemm_bf16_kernel(const float* __restrict__ h, float* __restrict__ out) {
    extern __shared__ __nv_bfloat16 smem[];
    __nv_bfloat16* Ah = smem;               // [128][LDA]
    __nv_bfloat16* Al = Ah + 128 * LDA;
    __nv_bfloat16* Bh = Al + 128 * LDA;     // [128 n][LDA k]
    __nv_bfloat16* Bl = Bh + 128 * LDA;

    const int g   = blockIdx.y;
    const int m0  = blockIdx.x * 128;
    const int tid = threadIdx.x;
    const int lane = tid & 31;
    const int warp = tid >> 5;
    const int mw = warp & 3;     // 0..3
    const int nw = warp >> 2;    // 0..1

    // A global mapping: 2 threads per row, 8 float4 each
    const int arow = tid >> 1;
    const int akq0 = (tid & 1) * 8;
    const float* gA = h + ((size_t)(m0 + arow) * G_ + g) * D_;
    const float invh = g_inv_h[(size_t)(m0 + arow) * G_ + g];

    // B global mapping: 2 threads per n-row, 4 uint4 (=32 bf16) each
    const int brow = tid >> 1;
    const int bq0  = (tid & 1) * 4;
    const uint4* gBh = reinterpret_cast<const uint4*>(
        g_wt_hi + ((size_t)g * KP + brow) * D_);
    const uint4* gBl = reinterpret_cast<const uint4*>(
        g_wt_lo + ((size_t)g * KP + brow) * D_);

    float acc[2][8][4];
#pragma unroll
    for (int mt = 0; mt < 2; mt++)
#pragma unroll
        for (int nt = 0; nt < 8; nt++)
#pragma unroll
            for (int r = 0; r < 4; r++) acc[mt][nt][r] = 0.f;

    for (int c = 0; c < NCHUNK; c++) {
        // ---- global loads into registers (overlap previous compute) ----
        float4 av[8];
#pragma unroll
        for (int i = 0; i < 8; i++)
            av[i] = *reinterpret_cast<const float4*>(gA + c * BKC + (akq0 + i) * 4);
        uint4 bvh[4], bvl[4];
#pragma unroll
        for (int i = 0; i < 4; i++) {
            bvh[i] = gBh[c * 8 + bq0 + i];
            bvl[i] = gBl[c * 8 + bq0 + i];
        }

        __syncthreads();   // previous compute done, smem free

        // ---- A: normalize, split, store ----
#pragma unroll
        for (int i = 0; i < 8; i++) {
            float x0 = av[i].x * invh, x1 = av[i].y * invh;
            float x2 = av[i].z * invh, x3 = av[i].w * invh;
            __nv_bfloat16 h0 = __float2bfloat16(x0), h1 = __float2bfloat16(x1);
            __nv_bfloat16 h2 = __float2bfloat16(x2), h3 = __float2bfloat16(x3);
            __nv_bfloat162 hp0 = {h0, h1}, hp1 = {h2, h3};
            __nv_bfloat162 lp0 = {__float2bfloat16(x0 - __bfloat162float(h0)),
                                  __float2bfloat16(x1 - __bfloat162float(h1))};
            __nv_bfloat162 lp1 = {__float2bfloat16(x2 - __bfloat162float(h2)),
                                  __float2bfloat16(x3 - __bfloat162float(h3))};
            int koff = (akq0 + i) * 4;
            uint2 uh, ul;
            uh.x = *reinterpret_cast<uint32_t*>(&hp0);
            uh.y = *reinterpret_cast<uint32_t*>(&hp1);
            ul.x = *reinterpret_cast<uint32_t*>(&lp0);
            ul.y = *reinterpret_cast<uint32_t*>(&lp1);
            *reinterpret_cast<uint2*>(Ah + arow * LDA + koff) = uh;
            *reinterpret_cast<uint2*>(Al + arow * LDA + koff) = ul;
        }
        // ---- B: store bf16 tiles ----
#pragma unroll
        for (int i = 0; i < 4; i++) {
            *reinterpret_cast<uint4*>(Bh + brow * LDA + (bq0 + i) * 8) = bvh[i];
            *reinterpret_cast<uint4*>(Bl + brow * LDA + (bq0 + i) * 8) = bvl[i];
        }
        __syncthreads();

        // ---- compute 4 k-steps of 16 ----
#pragma unroll
        for (int ks = 0; ks < 4; ks++) {
            uint32_t afh[2][4], afl[2][4];
#pragma unroll
            for (int mt = 0; mt < 2; mt++) {
                int rb = mw * 32 + mt * 16 + (lane >> 2);
                int kb = ks * 16 + (lane & 3) * 2;
                afh[mt][0] = *reinterpret_cast<uint32_t*>(Ah + rb * LDA + kb);
                afh[mt][1] = *reinterpret_cast<uint32_t*>(Ah + (rb + 8) * LDA + kb);
                afh[mt][2] = *reinterpret_cast<uint32_t*>(Ah + rb * LDA + kb + 8);
                afh[mt][3] = *reinterpret_cast<uint32_t*>(Ah + (rb + 8) * LDA + kb + 8);
                afl[mt][0] = *reinterpret_cast<uint32_t*>(Al + rb * LDA + kb);
                afl[mt][1] = *reinterpret_cast<uint32_t*>(Al + (rb + 8) * LDA + kb);
                afl[mt][2] = *reinterpret_cast<uint32_t*>(Al + rb * LDA + kb + 8);
                afl[mt][3] = *reinterpret_cast<uint32_t*>(Al + (rb + 8) * LDA + kb + 8);
            }
#pragma unroll
            for (int nt = 0; nt < 8; nt++) {
                int nb = nw * 64 + nt * 8 + (lane >> 2);
                int kb = ks * 16 + (lane & 3) * 2;
                uint32_t bh0 = *reinterpret_cast<uint32_t*>(Bh + nb * LDA + kb);
                uint32_t bh1 = *reinterpret_cast<uint32_t*>(Bh + nb * LDA + kb + 8);
                uint32_t bl0 = *reinterpret_cast<uint32_t*>(Bl + nb * LDA + kb);
                uint32_t bl1 = *reinterpret_cast<uint32_t*>(Bl + nb * LDA + kb + 8);
#pragma unroll
                for (int mt = 0; mt < 2; mt++) {
                    MMA_BF16(acc[mt][nt], afh[mt], bh0, bh1);
                    MMA_BF16(acc[mt][nt], afh[mt], bl0, bl1);
                    MMA_BF16(acc[mt][nt], afl[mt], bh0, bh1);
                }
            }
        }
    }

    // ---- epilogue: plain store (norms already applied) ----
#pragma unroll
    for (int mt = 0; mt < 2; mt++) {
        int r0 = m0 + mw * 32 + mt * 16 + (lane >> 2);
#pragma unroll
        for (int nt = 0; nt < 8; nt++) {
            int c0 = nw * 64 + nt * 8 + (lane & 3) * 2;
            if (c0 < K_) {
                float2 v0 = {acc[mt][nt][0], acc[mt][nt][1]};
                float2 v1 = {acc[mt][nt][2], acc[mt][nt][3]};
                *reinterpret_cast<float2*>(
                    out + ((size_t)r0 * G_ + g) * K_ + c0) = v0;
                *reinterpret_cast<float2*>(
                    out + ((size_t)(r0 + 8) * G_ + g) * K_ + c0) = v1;
            }
        }
    }
}

// ---------------------------------------------------------------------------
extern "C" void kernel_launch(void* const* d_in, const int* in_sizes, int n_in,
                              void* d_out, int out_size) {
    const float* h = (const float*)d_in[0];   // [512,100,768]
    const float* w = (const float*)d_in[1];   // [100,768,100]
    float* out = (float*)d_out;               // [512,100,100]
    (void)in_sizes; (void)n_in; (void)out_size;

    const int smem_bytes = 4 * 128 * LDA * 2;  // 73728
    cudaFuncSetAttribute(gemm_bf16_kernel,
                         cudaFuncAttributeMaxDynamicSharedMemorySize, smem_bytes);

    norm_h_kernel<<<(B_ * G_) / 8, 256>>>(h);
    norm_w_kernel<<<G_, 512>>>(w);
    split_w_kernel<<<dim3(NCHUNK, G_), 256>>>(w);
    dim3 grid(B_ / 128, G_);
    gemm_bf16_kernel<<<grid, 256, smem_bytes>>>(h, out);
}

// round 4
// speedup vs baseline: 1.5234x; 1.3244x over previous
#include <cuda_runtime.h>
#include <cuda_bf16.h>
#include <cstdint>

// out[b,g,k] = sum_d (h[b,g,d]/||h||) * (w[g,d,k]/||w_col||)
// B=512, G=100, D=768, K=100.
// bf16 two-term split (x ~ hi+lo), 3-product HMMA (mma.sync m16n8k16),
// ldmatrix fragment loads, double-buffered smem, cp.async for B.

#define B_ 512
#define G_ 100
#define D_ 768
#define K_ 100
#define KP 128
#define BKC 64              // k-chunk
#define NCHUNK (D_ / BKC)   // 12
#define LDB 144             // smem row stride in BYTES (72 bf16) -> conflict-free

#define STAGE_BYTES 73728   // Ah(18432) Al Bh Bl
#define AH_OFF 0
#define AL_OFF 18432
#define BH_OFF 36864
#define BL_OFF 55296

// ---------------- device scratch ----------------
__device__ float g_inv_h[B_ * G_];
__device__ float g_inv_w[G_ * K_];
__device__ __nv_bfloat16 g_wt_hi[(size_t)G_ * KP * D_];
__device__ __nv_bfloat16 g_wt_lo[(size_t)G_ * KP * D_];

// ---------------- helpers ----------------
__device__ __forceinline__ uint32_t smem_u32(const void* p) {
    uint32_t a;
    asm("{ .reg .u64 t; cvta.to.shared.u64 t, %1; cvt.u32.u64 %0, t; }"
        : "=r"(a) : "l"(p));
    return a;
}

#define MMA_BF16(d, a, b0, b1)                                              \
    asm volatile(                                                           \
        "mma.sync.aligned.m16n8k16.row.col.f32.bf16.bf16.f32 "              \
        "{%0,%1,%2,%3}, {%4,%5,%6,%7}, {%8,%9}, {%0,%1,%2,%3};"             \
        : "+f"(d[0]), "+f"(d[1]), "+f"(d[2]), "+f"(d[3])                    \
        : "r"(a[0]), "r"(a[1]), "r"(a[2]), "r"(a[3]), "r"(b0), "r"(b1))

#define LDSM4(r, addr)                                                      \
    asm volatile("ldmatrix.sync.aligned.m8n8.x4.shared.b16 "                \
                 "{%0,%1,%2,%3}, [%4];"                                     \
                 : "=r"((r)[0]), "=r"((r)[1]), "=r"((r)[2]), "=r"((r)[3])   \
                 : "r"(addr))

#define CP16(dst, src)                                                      \
    asm volatile("cp.async.cg.shared.global [%0], [%1], 16;"                \
                 :: "r"(dst), "l"(src) : "memory")
#define CP_COMMIT() asm volatile("cp.async.commit_group;" ::: "memory")
#define CP_WAIT0()  asm volatile("cp.async.wait_group 0;" ::: "memory")

// ---------------------------------------------------------------------------
__global__ void norm_h_kernel(const float* __restrict__ h) {
    int warp = (blockIdx.x * blockDim.x + threadIdx.x) >> 5;
    int lane = threadIdx.x & 31;
    if (warp >= B_ * G_) return;
    const float4* p = reinterpret_cast<const float4*>(h + (size_t)warp * D_);
    float s = 0.f;
#pragma unroll
    for (int t = 0; t < 6; t++) {
        float4 v = p[lane + 32 * t];
        s += v.x * v.x + v.y * v.y + v.z * v.z + v.w * v.w;
    }
#pragma unroll
    for (int o = 16; o; o >>= 1) s += __shfl_xor_sync(0xffffffffu, s, o);
    if (lane == 0) g_inv_h[warp] = 1.0f / fmaxf(sqrtf(s), 1e-12f);
}

__global__ void norm_w_kernel(const float* __restrict__ w) {
    __shared__ float partial[4][128];
    int g = blockIdx.x;
    int k = threadIdx.x & 127;
    int c = threadIdx.x >> 7;
    float s = 0.f;
    if (k < K_) {
        const float* base = w + (size_t)g * D_ * K_ + (size_t)c * 192 * K_ + k;
#pragma unroll 8
        for (int d = 0; d < 192; d++) {
            float v = base[(size_t)d * K_];
            s += v * v;
        }
    }
    partial[c][k] = s;
    __syncthreads();
    if (c == 0 && k < K_) {
        float t = partial[0][k] + partial[1][k] + partial[2][k] + partial[3][k];
        g_inv_w[g * K_ + k] = 1.0f / fmaxf(sqrtf(t), 1e-12f);
    }
}

__global__ void split_w_kernel(const float* __restrict__ w) {
    __shared__ float ws[64][104];
    const int dc = blockIdx.x;
    const int g  = blockIdx.y;
    const int tid = threadIdx.x;
    const float* src = w + (size_t)g * D_ * K_ + (size_t)dc * 64 * K_;
#pragma unroll
    for (int i = 0; i < 25; i++) {
        int idx = tid + 256 * i;
        ws[idx / K_][idx % K_] = src[idx];
    }
    __syncthreads();
    const int k  = tid >> 1;
    const int d0 = (tid & 1) * 32;
    float invw = (k < K_) ? g_inv_w[g * K_ + k] : 0.f;
    __nv_bfloat16 hb[32], lb[32];
#pragma unroll
    for (int j = 0; j < 32; j++) {
        float x = (k < K_) ? ws[d0 + j][k] * invw : 0.f;
        __nv_bfloat16 hi = __float2bfloat16(x);
        hb[j] = hi;
        lb[j] = __float2bfloat16(x - __bfloat162float(hi));
    }
    size_t base = ((size_t)g * KP + k) * D_ + (size_t)dc * 64 + d0;
    uint4* dh = reinterpret_cast<uint4*>(g_wt_hi + base);
    uint4* dl = reinterpret_cast<uint4*>(g_wt_lo + base);
#pragma unroll
    for (int q = 0; q < 4; q++) {
        dh[q] = *reinterpret_cast<const uint4*>(hb + q * 8);
        dl[q] = *reinterpret_cast<const uint4*>(lb + q * 8);
    }
}

// ---------------------------------------------------------------------------
// HMMA GEMM. CTA = (g, 128 rows). 8 warps: mw = warp&1 (64 rows),
// nw = warp>>1 (32 cols). Warp tile 64x32, 3 bf16 products, fp32 acc.
// ---------------------------------------------------------------------------
__global__ __launch_bounds__(256)
void gemm_hmma_kernel(const float* __restrict__ h, float* __restrict__ out) {
    extern __shared__ char smem[];
    const uint32_t sb = smem_u32(smem);
    const int tid  = threadIdx.x;
    const int lane = tid & 31;
    const int warp = tid >> 5;
    const int mw = warp & 1;
    const int nw = warp >> 1;
    const int g  = blockIdx.y;
    const int m0 = blockIdx.x * 128;

    // ---- global load mapping: 2 threads per row, 32 elems each ----
    const int arow = tid >> 1;
    const int koff = (tid & 1) * 32;                 // element offset in chunk
    const float* gA = h + ((size_t)(m0 + arow) * G_ + g) * D_ + koff;
    const float invh = g_inv_h[(size_t)(m0 + arow) * G_ + g];
    const char* gBh = reinterpret_cast<const char*>(
        g_wt_hi + ((size_t)g * KP + arow) * D_ + koff);
    const char* gBl = reinterpret_cast<const char*>(
        g_wt_lo + ((size_t)g * KP + arow) * D_ + koff);

    // smem store offsets (bytes) within a stage
    const uint32_t srow = arow * LDB + (tid & 1) * 64;

    // ldmatrix base addresses (stage-relative)
    const uint32_t a_lm = (mw * 64 + (lane & 15)) * LDB + (lane >> 4) * 16;
    const uint32_t b_lm = (nw * 32 + (lane & 7) + ((lane >> 4) & 1) * 8) * LDB
                        + ((lane >> 3) & 1) * 16;

    float acc[4][4][4];   // [mt][nf][reg]
#pragma unroll
    for (int mt = 0; mt < 4; mt++)
#pragma unroll
        for (int nf = 0; nf < 4; nf++)
#pragma unroll
            for (int r = 0; r < 4; r++) acc[mt][nf][r] = 0.f;

    // ---- A convert+store helper (32 elems -> hi/lo bf16) ----
    auto store_A = [&](const float4* av, uint32_t stage) {
        uint32_t uh[16], ul[16];
#pragma unroll
        for (int i = 0; i < 8; i++) {
            float x0 = av[i].x * invh, x1 = av[i].y * invh;
            float x2 = av[i].z * invh, x3 = av[i].w * invh;
            __nv_bfloat162 h0 = __float22bfloat162_rn(make_float2(x0, x1));
            __nv_bfloat162 h1 = __float22bfloat162_rn(make_float2(x2, x3));
            float2 f0 = __bfloat1622float2(h0), f1 = __bfloat1622float2(h1);
            __nv_bfloat162 l0 = __float22bfloat162_rn(make_float2(x0 - f0.x, x1 - f0.y));
            __nv_bfloat162 l1 = __float22bfloat162_rn(make_float2(x2 - f1.x, x3 - f1.y));
            uh[i * 2]     = *reinterpret_cast<uint32_t*>(&h0);
            uh[i * 2 + 1] = *reinterpret_cast<uint32_t*>(&h1);
            ul[i * 2]     = *reinterpret_cast<uint32_t*>(&l0);
            ul[i * 2 + 1] = *reinterpret_cast<uint32_t*>(&l1);
        }
#pragma unroll
        for (int i = 0; i < 4; i++) {
            asm volatile("st.shared.v4.b32 [%0], {%1,%2,%3,%4};"
                :: "r"(stage + AH_OFF + srow + i * 16),
                   "r"(uh[i*4]), "r"(uh[i*4+1]), "r"(uh[i*4+2]), "r"(uh[i*4+3]) : "memory");
            asm volatile("st.shared.v4.b32 [%0], {%1,%2,%3,%4};"
                :: "r"(stage + AL_OFF + srow + i * 16),
                   "r"(ul[i*4]), "r"(ul[i*4+1]), "r"(ul[i*4+2]), "r"(ul[i*4+3]) : "memory");
        }
    };

    auto cp_B = [&](int c, uint32_t stage) {
#pragma unroll
        for (int i = 0; i < 4; i++) {
            CP16(stage + BH_OFF + srow + i * 16, gBh + (size_t)c * 128 + i * 16);
            CP16(stage + BL_OFF + srow + i * 16, gBl + (size_t)c * 128 + i * 16);
        }
    };

    // ---- prologue: fill stage 0 ----
    {
        float4 av[8];
#pragma unroll
        for (int i = 0; i < 8; i++)
            av[i] = *reinterpret_cast<const float4*>(gA + i * 4);
        cp_B(0, sb);
        CP_COMMIT();
        store_A(av, sb);
        CP_WAIT0();
    }
    __syncthreads();

    for (int c = 0; c < NCHUNK; c++) {
        const uint32_t stage  = sb + (uint32_t)(c & 1) * STAGE_BYTES;
        const uint32_t nstage = sb + (uint32_t)((c + 1) & 1) * STAGE_BYTES;

        // prefetch next chunk
        float4 av[8];
        if (c + 1 < NCHUNK) {
#pragma unroll
            for (int i = 0; i < 8; i++)
                av[i] = *reinterpret_cast<const float4*>(gA + (c + 1) * BKC + i * 4);
            cp_B(c + 1, nstage);
            CP_COMMIT();
        }

        // ---- compute current chunk ----
#pragma unroll
        for (int ks = 0; ks < 4; ks++) {
            const uint32_t ko = ks * 32;
            uint32_t ah[4][4], al[4][4];
#pragma unroll
            for (int mt = 0; mt < 4; mt++) {
                LDSM4(ah[mt], stage + AH_OFF + a_lm + mt * (16 * LDB) + ko);
                LDSM4(al[mt], stage + AL_OFF + a_lm + mt * (16 * LDB) + ko);
            }
#pragma unroll
            for (int ng = 0; ng < 2; ng++) {
                uint32_t bh[4], bl[4];
                LDSM4(bh, stage + BH_OFF + b_lm + ng * (16 * LDB) + ko);
                LDSM4(bl, stage + BL_OFF + b_lm + ng * (16 * LDB) + ko);
                // product-major: same acc re-touched every 8 MMAs
#pragma unroll
                for (int mt = 0; mt < 4; mt++) {
                    MMA_BF16(acc[mt][ng * 2],     ah[mt], bh[0], bh[1]);
                    MMA_BF16(acc[mt][ng * 2 + 1], ah[mt], bh[2], bh[3]);
                }
#pragma unroll
                for (int mt = 0; mt < 4; mt++) {
                    MMA_BF16(acc[mt][ng * 2],     ah[mt], bl[0], bl[1]);
                    MMA_BF16(acc[mt][ng * 2 + 1], ah[mt], bl[2], bl[3]);
                }
#pragma unroll
                for (int mt = 0; mt < 4; mt++) {
                    MMA_BF16(acc[mt][ng * 2],     al[mt], bh[0], bh[1]);
                    MMA_BF16(acc[mt][ng * 2 + 1], al[mt], bh[2], bh[3]);
                }
            }
        }

        if (c + 1 < NCHUNK) {
            store_A(av, nstage);
            CP_WAIT0();
        }
        __syncthreads();
    }

    // ---- epilogue ----
#pragma unroll
    for (int mt = 0; mt < 4; mt++) {
        const int row = m0 + mw * 64 + mt * 16 + (lane >> 2);
#pragma unroll
        for (int nf = 0; nf < 4; nf++) {
            const int col = nw * 32 + nf * 8 + (lane & 3) * 2;
            if (col < K_) {
                float2 v0 = {acc[mt][nf][0], acc[mt][nf][1]};
                float2 v1 = {acc[mt][nf][2], acc[mt][nf][3]};
                *reinterpret_cast<float2*>(out + ((size_t)row * G_ + g) * K_ + col) = v0;
                *reinterpret_cast<float2*>(out + ((size_t)(row + 8) * G_ + g) * K_ + col) = v1;
            }
        }
    }
}

// ---------------------------------------------------------------------------
extern "C" void kernel_launch(void* const* d_in, const int* in_sizes, int n_in,
                              void* d_out, int out_size) {
    const float* h = (const float*)d_in[0];   // [512,100,768]
    const float* w = (const float*)d_in[1];   // [100,768,100]
    float* out = (float*)d_out;               // [512,100,100]
    (void)in_sizes; (void)n_in; (void)out_size;

    const int smem_bytes = 2 * STAGE_BYTES;   // 147456
    cudaFuncSetAttribute(gemm_hmma_kernel,
                         cudaFuncAttributeMaxDynamicSharedMemorySize, smem_bytes);

    norm_h_kernel<<<(B_ * G_) / 8, 256>>>(h);
    norm_w_kernel<<<G_, 512>>>(w);
    split_w_kernel<<<dim3(NCHUNK, G_), 256>>>(w);
    dim3 grid(B_ / 128, G_);
    gemm_hmma_kernel<<<grid, 256, smem_bytes>>>(h, out);
}

// round 5
// speedup vs baseline: 1.6904x; 1.1096x over previous
#include <cuda_runtime.h>
#include <cuda_bf16.h>
#include <cstdint>

// out[b,g,k] = sum_d (h[b,g,d]/||h||) * (w[g,d,k]/||w_col||)
// B=512, G=100, D=768, K=100.
// bf16 two-term split (x ~ hi+lo), 3-product HMMA (mma.sync m16n8k16),
// ldmatrix fragment loads, double-buffered smem, cp.async for B.
// 512 threads, 4x4 warp grid, warp tile 32x32.

#define B_ 512
#define G_ 100
#define D_ 768
#define K_ 100
#define KP 128
#define BKC 64              // k-chunk
#define NCHUNK (D_ / BKC)   // 12
#define LDB 144             // smem row stride in BYTES -> conflict-free ldmatrix

#define STAGE_BYTES 73728   // Ah(18432) Al Bh Bl
#define AH_OFF 0
#define AL_OFF 18432
#define BH_OFF 36864
#define BL_OFF 55296

// ---------------- device scratch ----------------
__device__ float g_inv_h[B_ * G_];
__device__ float g_inv_w[G_ * K_];
__device__ __nv_bfloat16 g_wt_hi[(size_t)G_ * KP * D_];
__device__ __nv_bfloat16 g_wt_lo[(size_t)G_ * KP * D_];

// ---------------- helpers ----------------
__device__ __forceinline__ uint32_t smem_u32(const void* p) {
    uint32_t a;
    asm("{ .reg .u64 t; cvta.to.shared.u64 t, %1; cvt.u32.u64 %0, t; }"
        : "=r"(a) : "l"(p));
    return a;
}

#define MMA_BF16(d, a, b0, b1)                                              \
    asm volatile(                                                           \
        "mma.sync.aligned.m16n8k16.row.col.f32.bf16.bf16.f32 "              \
        "{%0,%1,%2,%3}, {%4,%5,%6,%7}, {%8,%9}, {%0,%1,%2,%3};"             \
        : "+f"(d[0]), "+f"(d[1]), "+f"(d[2]), "+f"(d[3])                    \
        : "r"(a[0]), "r"(a[1]), "r"(a[2]), "r"(a[3]), "r"(b0), "r"(b1))

#define LDSM4(r, addr)                                                      \
    asm volatile("ldmatrix.sync.aligned.m8n8.x4.shared.b16 "                \
                 "{%0,%1,%2,%3}, [%4];"                                     \
                 : "=r"((r)[0]), "=r"((r)[1]), "=r"((r)[2]), "=r"((r)[3])   \
                 : "r"(addr))

#define CP16(dst, src)                                                      \
    asm volatile("cp.async.cg.shared.global [%0], [%1], 16;"                \
                 :: "r"(dst), "l"(src) : "memory")
#define CP_COMMIT() asm volatile("cp.async.commit_group;" ::: "memory")
#define CP_WAIT0()  asm volatile("cp.async.wait_group 0;" ::: "memory")

// ---------------------------------------------------------------------------
__global__ void norm_h_kernel(const float* __restrict__ h) {
    int warp = (blockIdx.x * blockDim.x + threadIdx.x) >> 5;
    int lane = threadIdx.x & 31;
    if (warp >= B_ * G_) return;
    const float4* p = reinterpret_cast<const float4*>(h + (size_t)warp * D_);
    float s = 0.f;
#pragma unroll
    for (int t = 0; t < 6; t++) {
        float4 v = p[lane + 32 * t];
        s += v.x * v.x + v.y * v.y + v.z * v.z + v.w * v.w;
    }
#pragma unroll
    for (int o = 16; o; o >>= 1) s += __shfl_xor_sync(0xffffffffu, s, o);
    if (lane == 0) g_inv_h[warp] = 1.0f / fmaxf(sqrtf(s), 1e-12f);
}

__global__ void norm_w_kernel(const float* __restrict__ w) {
    __shared__ float partial[4][128];
    int g = blockIdx.x;
    int k = threadIdx.x & 127;
    int c = threadIdx.x >> 7;
    float s = 0.f;
    if (k < K_) {
        const float* base = w + (size_t)g * D_ * K_ + (size_t)c * 192 * K_ + k;
#pragma unroll 8
        for (int d = 0; d < 192; d++) {
            float v = base[(size_t)d * K_];
            s += v * v;
        }
    }
    partial[c][k] = s;
    __syncthreads();
    if (c == 0 && k < K_) {
        float t = partial[0][k] + partial[1][k] + partial[2][k] + partial[3][k];
        g_inv_w[g * K_ + k] = 1.0f / fmaxf(sqrtf(t), 1e-12f);
    }
}

__global__ void split_w_kernel(const float* __restrict__ w) {
    __shared__ float ws[64][104];
    const int dc = blockIdx.x;
    const int g  = blockIdx.y;
    const int tid = threadIdx.x;
    const float* src = w + (size_t)g * D_ * K_ + (size_t)dc * 64 * K_;
#pragma unroll
    for (int i = 0; i < 25; i++) {
        int idx = tid + 256 * i;
        ws[idx / K_][idx % K_] = src[idx];
    }
    __syncthreads();
    const int k  = tid >> 1;
    const int d0 = (tid & 1) * 32;
    float invw = (k < K_) ? g_inv_w[g * K_ + k] : 0.f;
    __nv_bfloat16 hb[32], lb[32];
#pragma unroll
    for (int j = 0; j < 32; j++) {
        float x = (k < K_) ? ws[d0 + j][k] * invw : 0.f;
        __nv_bfloat16 hi = __float2bfloat16(x);
        hb[j] = hi;
        lb[j] = __float2bfloat16(x - __bfloat162float(hi));
    }
    size_t base = ((size_t)g * KP + k) * D_ + (size_t)dc * 64 + d0;
    uint4* dh = reinterpret_cast<uint4*>(g_wt_hi + base);
    uint4* dl = reinterpret_cast<uint4*>(g_wt_lo + base);
#pragma unroll
    for (int q = 0; q < 4; q++) {
        dh[q] = *reinterpret_cast<const uint4*>(hb + q * 8);
        dl[q] = *reinterpret_cast<const uint4*>(lb + q * 8);
    }
}

// ---------------------------------------------------------------------------
// HMMA GEMM. CTA = (g, 128 rows). 16 warps: mw = warp&3 (32 rows),
// nw = warp>>2 (32 cols). Warp tile 32x32, 3 bf16 products, fp32 acc.
// ---------------------------------------------------------------------------
__global__ __launch_bounds__(512)
void gemm_hmma_kernel(const float* __restrict__ h, float* __restrict__ out) {
    extern __shared__ char smem[];
    const uint32_t sb = smem_u32(smem);
    const int tid  = threadIdx.x;
    const int lane = tid & 31;
    const int warp = tid >> 5;
    const int mw = warp & 3;
    const int nw = warp >> 2;
    const int g  = blockIdx.y;
    const int m0 = blockIdx.x * 128;

    // ---- global load mapping: 4 threads per row, 16 elems each ----
    const int arow = tid >> 2;
    const int q    = tid & 3;
    const float* gA = h + ((size_t)(m0 + arow) * G_ + g) * D_ + q * 16;
    const float invh = g_inv_h[(size_t)(m0 + arow) * G_ + g];
    const char* gBh = reinterpret_cast<const char*>(
        g_wt_hi + ((size_t)g * KP + arow) * D_) + q * 32;
    const char* gBl = reinterpret_cast<const char*>(
        g_wt_lo + ((size_t)g * KP + arow) * D_) + q * 32;

    // smem store offsets (bytes) within a stage
    const uint32_t srow = arow * LDB + q * 32;

    // ldmatrix base addresses (stage-relative)
    const uint32_t a_lm = (mw * 32 + (lane & 15)) * LDB + (lane >> 4) * 16;
    const uint32_t b_lm = (nw * 32 + (lane & 7) + ((lane >> 4) & 1) * 8) * LDB
                        + ((lane >> 3) & 1) * 16;

    float acc[2][4][4];   // [mt][nf][reg]
#pragma unroll
    for (int mt = 0; mt < 2; mt++)
#pragma unroll
        for (int nf = 0; nf < 4; nf++)
#pragma unroll
            for (int r = 0; r < 4; r++) acc[mt][nf][r] = 0.f;

    // ---- A convert+store: 16 fp32 -> hi/lo bf16 (32B each) ----
    auto store_A = [&](const float4* av, uint32_t stage) {
        uint32_t uh[8], ul[8];
#pragma unroll
        for (int i = 0; i < 4; i++) {
            float x0 = av[i].x * invh, x1 = av[i].y * invh;
            float x2 = av[i].z * invh, x3 = av[i].w * invh;
            __nv_bfloat162 h0 = __float22bfloat162_rn(make_float2(x0, x1));
            __nv_bfloat162 h1 = __float22bfloat162_rn(make_float2(x2, x3));
            float2 f0 = __bfloat1622float2(h0), f1 = __bfloat1622float2(h1);
            __nv_bfloat162 l0 = __float22bfloat162_rn(make_float2(x0 - f0.x, x1 - f0.y));
            __nv_bfloat162 l1 = __float22bfloat162_rn(make_float2(x2 - f1.x, x3 - f1.y));
            uh[i * 2]     = *reinterpret_cast<uint32_t*>(&h0);
            uh[i * 2 + 1] = *reinterpret_cast<uint32_t*>(&h1);
            ul[i * 2]     = *reinterpret_cast<uint32_t*>(&l0);
            ul[i * 2 + 1] = *reinterpret_cast<uint32_t*>(&l1);
        }
        asm volatile("st.shared.v4.b32 [%0], {%1,%2,%3,%4};"
            :: "r"(stage + AH_OFF + srow), "r"(uh[0]), "r"(uh[1]), "r"(uh[2]), "r"(uh[3]) : "memory");
        asm volatile("st.shared.v4.b32 [%0], {%1,%2,%3,%4};"
            :: "r"(stage + AH_OFF + srow + 16), "r"(uh[4]), "r"(uh[5]), "r"(uh[6]), "r"(uh[7]) : "memory");
        asm volatile("st.shared.v4.b32 [%0], {%1,%2,%3,%4};"
            :: "r"(stage + AL_OFF + srow), "r"(ul[0]), "r"(ul[1]), "r"(ul[2]), "r"(ul[3]) : "memory");
        asm volatile("st.shared.v4.b32 [%0], {%1,%2,%3,%4};"
            :: "r"(stage + AL_OFF + srow + 16), "r"(ul[4]), "r"(ul[5]), "r"(ul[6]), "r"(ul[7]) : "memory");
    };

    auto cp_B = [&](int c, uint32_t stage) {
        CP16(stage + BH_OFF + srow,      gBh + (size_t)c * 128);
        CP16(stage + BH_OFF + srow + 16, gBh + (size_t)c * 128 + 16);
        CP16(stage + BL_OFF + srow,      gBl + (size_t)c * 128);
        CP16(stage + BL_OFF + srow + 16, gBl + (size_t)c * 128 + 16);
    };

    // ---- prologue: fill stage 0 ----
    {
        float4 av[4];
#pragma unroll
        for (int i = 0; i < 4; i++)
            av[i] = *reinterpret_cast<const float4*>(gA + i * 4);
        cp_B(0, sb);
        CP_COMMIT();
        store_A(av, sb);
        CP_WAIT0();
    }
    __syncthreads();

    for (int c = 0; c < NCHUNK; c++) {
        const uint32_t stage  = sb + (uint32_t)(c & 1) * STAGE_BYTES;
        const uint32_t nstage = sb + (uint32_t)((c + 1) & 1) * STAGE_BYTES;

        // prefetch next chunk
        float4 av[4];
        if (c + 1 < NCHUNK) {
#pragma unroll
            for (int i = 0; i < 4; i++)
                av[i] = *reinterpret_cast<const float4*>(gA + (c + 1) * BKC + i * 4);
            cp_B(c + 1, nstage);
            CP_COMMIT();
        }

        // ---- compute current chunk ----
#pragma unroll
        for (int ks = 0; ks < 4; ks++) {
            const uint32_t ko = ks * 32;
            uint32_t ah[2][4], al[2][4];
#pragma unroll
            for (int mt = 0; mt < 2; mt++) {
                LDSM4(ah[mt], stage + AH_OFF + a_lm + mt * (16 * LDB) + ko);
                LDSM4(al[mt], stage + AL_OFF + a_lm + mt * (16 * LDB) + ko);
            }
            uint32_t bh[2][4], bl[2][4];
#pragma unroll
            for (int ng = 0; ng < 2; ng++) {
                LDSM4(bh[ng], stage + BH_OFF + b_lm + ng * (16 * LDB) + ko);
                LDSM4(bl[ng], stage + BL_OFF + b_lm + ng * (16 * LDB) + ko);
            }
            // product-major: same acc re-touched every 8 MMAs
#pragma unroll
            for (int mt = 0; mt < 2; mt++)
#pragma unroll
                for (int nf = 0; nf < 4; nf++)
                    MMA_BF16(acc[mt][nf], ah[mt],
                             bh[nf >> 1][(nf & 1) * 2], bh[nf >> 1][(nf & 1) * 2 + 1]);
#pragma unroll
            for (int mt = 0; mt < 2; mt++)
#pragma unroll
                for (int nf = 0; nf < 4; nf++)
                    MMA_BF16(acc[mt][nf], ah[mt],
                             bl[nf >> 1][(nf & 1) * 2], bl[nf >> 1][(nf & 1) * 2 + 1]);
#pragma unroll
            for (int mt = 0; mt < 2; mt++)
#pragma unroll
                for (int nf = 0; nf < 4; nf++)
                    MMA_BF16(acc[mt][nf], al[mt],
                             bh[nf >> 1][(nf & 1) * 2], bh[nf >> 1][(nf & 1) * 2 + 1]);
        }

        if (c + 1 < NCHUNK) {
            store_A(av, nstage);
            CP_WAIT0();
        }
        __syncthreads();
    }

    // ---- epilogue ----
#pragma unroll
    for (int mt = 0; mt < 2; mt++) {
        const int row = m0 + mw * 32 + mt * 16 + (lane >> 2);
#pragma unroll
        for (int nf = 0; nf < 4; nf++) {
            const int col = nw * 32 + nf * 8 + (lane & 3) * 2;
            if (col < K_) {
                float2 v0 = {acc[mt][nf][0], acc[mt][nf][1]};
                float2 v1 = {acc[mt][nf][2], acc[mt][nf][3]};
                *reinterpret_cast<float2*>(out + ((size_t)row * G_ + g) * K_ + col) = v0;
                *reinterpret_cast<float2*>(out + ((size_t)(row + 8) * G_ + g) * K_ + col) = v1;
            }
        }
    }
}

// ---------------------------------------------------------------------------
extern "C" void kernel_launch(void* const* d_in, const int* in_sizes, int n_in,
                              void* d_out, int out_size) {
    const float* h = (const float*)d_in[0];   // [512,100,768]
    const float* w = (const float*)d_in[1];   // [100,768,100]
    float* out = (float*)d_out;               // [512,100,100]
    (void)in_sizes; (void)n_in; (void)out_size;

    const int smem_bytes = 2 * STAGE_BYTES;   // 147456
    cudaFuncSetAttribute(gemm_hmma_kernel,
                         cudaFuncAttributeMaxDynamicSharedMemorySize, smem_bytes);

    norm_h_kernel<<<(B_ * G_) / 8, 256>>>(h);
    norm_w_kernel<<<G_, 512>>>(w);
    split_w_kernel<<<dim3(NCHUNK, G_), 256>>>(w);
    dim3 grid(B_ / 128, G_);
    gemm_hmma_kernel<<<grid, 512, smem_bytes>>>(h, out);
}

// round 6
// speedup vs baseline: 1.7596x; 1.0409x over previous
#include <cuda_runtime.h>
#include <cuda_bf16.h>
#include <cstdint>

// out[b,g,k] = sum_d (h[b,g,d]/||h||) * (w[g,d,k]/||w_col||)
// B=512, G=100, D=768, K=100.
// bf16 two-term split, 3-product HMMA, ldmatrix, double-buffered smem.
// 256 threads, 2x4 warp grid, warp tile 64x32, BKC=32, 2 CTAs/SM.

#define B_ 512
#define G_ 100
#define D_ 768
#define K_ 100
#define KP 128
#define BKC 32              // k-chunk
#define NCHUNK (D_ / BKC)   // 24
#define LDB 80              // smem row stride bytes (32 bf16 + pad)

#define TILE_BYTES 10240    // 128 rows * LDB
#define AH_OFF 0
#define AL_OFF 10240
#define BH_OFF 20480
#define BL_OFF 30720
#define STAGE_BYTES 40960

// ---------------- device scratch ----------------
__device__ float g_inv_h[B_ * G_];
__device__ float g_inv_w[G_ * K_];
__device__ __nv_bfloat16 g_wt_hi[(size_t)G_ * KP * D_];
__device__ __nv_bfloat16 g_wt_lo[(size_t)G_ * KP * D_];

// ---------------- helpers ----------------
__device__ __forceinline__ uint32_t smem_u32(const void* p) {
    uint32_t a;
    asm("{ .reg .u64 t; cvta.to.shared.u64 t, %1; cvt.u32.u64 %0, t; }"
        : "=r"(a) : "l"(p));
    return a;
}

#define MMA_BF16(d, a, b0, b1)                                              \
    asm volatile(                                                           \
        "mma.sync.aligned.m16n8k16.row.col.f32.bf16.bf16.f32 "              \
        "{%0,%1,%2,%3}, {%4,%5,%6,%7}, {%8,%9}, {%0,%1,%2,%3};"             \
        : "+f"(d[0]), "+f"(d[1]), "+f"(d[2]), "+f"(d[3])                    \
        : "r"(a[0]), "r"(a[1]), "r"(a[2]), "r"(a[3]), "r"(b0), "r"(b1))

#define LDSM4(r, addr)                                                      \
    asm volatile("ldmatrix.sync.aligned.m8n8.x4.shared.b16 "                \
                 "{%0,%1,%2,%3}, [%4];"                                     \
                 : "=r"((r)[0]), "=r"((r)[1]), "=r"((r)[2]), "=r"((r)[3])   \
                 : "r"(addr))

#define CP16(dst, src)                                                      \
    asm volatile("cp.async.cg.shared.global [%0], [%1], 16;"                \
                 :: "r"(dst), "l"(src) : "memory")
#define CP_COMMIT() asm volatile("cp.async.commit_group;" ::: "memory")
#define CP_WAIT0()  asm volatile("cp.async.wait_group 0;" ::: "memory")

// ---------------------------------------------------------------------------
__global__ void norm_h_kernel(const float* __restrict__ h) {
    int warp = (blockIdx.x * blockDim.x + threadIdx.x) >> 5;
    int lane = threadIdx.x & 31;
    if (warp >= B_ * G_) return;
    const float4* p = reinterpret_cast<const float4*>(h + (size_t)warp * D_);
    float s = 0.f;
#pragma unroll
    for (int t = 0; t < 6; t++) {
        float4 v = p[lane + 32 * t];
        s += v.x * v.x + v.y * v.y + v.z * v.z + v.w * v.w;
    }
#pragma unroll
    for (int o = 16; o; o >>= 1) s += __shfl_xor_sync(0xffffffffu, s, o);
    if (lane == 0) g_inv_h[warp] = 1.0f / fmaxf(sqrtf(s), 1e-12f);
}

__global__ void norm_w_kernel(const float* __restrict__ w) {
    __shared__ float partial[4][128];
    int g = blockIdx.x;
    int k = threadIdx.x & 127;
    int c = threadIdx.x >> 7;
    float s = 0.f;
    if (k < K_) {
        const float* base = w + (size_t)g * D_ * K_ + (size_t)c * 192 * K_ + k;
#pragma unroll 8
        for (int d = 0; d < 192; d++) {
            float v = base[(size_t)d * K_];
            s += v * v;
        }
    }
    partial[c][k] = s;
    __syncthreads();
    if (c == 0 && k < K_) {
        float t = partial[0][k] + partial[1][k] + partial[2][k] + partial[3][k];
        g_inv_w[g * K_ + k] = 1.0f / fmaxf(sqrtf(t), 1e-12f);
    }
}

__global__ void split_w_kernel(const float* __restrict__ w) {
    __shared__ float ws[64][104];
    const int dc = blockIdx.x;
    const int g  = blockIdx.y;
    const int tid = threadIdx.x;
    const float* src = w + (size_t)g * D_ * K_ + (size_t)dc * 64 * K_;
#pragma unroll
    for (int i = 0; i < 25; i++) {
        int idx = tid + 256 * i;
        ws[idx / K_][idx % K_] = src[idx];
    }
    __syncthreads();
    const int k  = tid >> 1;
    const int d0 = (tid & 1) * 32;
    float invw = (k < K_) ? g_inv_w[g * K_ + k] : 0.f;
    __nv_bfloat16 hb[32], lb[32];
#pragma unroll
    for (int j = 0; j < 32; j++) {
        float x = (k < K_) ? ws[d0 + j][k] * invw : 0.f;
        __nv_bfloat16 hi = __float2bfloat16(x);
        hb[j] = hi;
        lb[j] = __float2bfloat16(x - __bfloat162float(hi));
    }
    size_t base = ((size_t)g * KP + k) * D_ + (size_t)dc * 64 + d0;
    uint4* dh = reinterpret_cast<uint4*>(g_wt_hi + base);
    uint4* dl = reinterpret_cast<uint4*>(g_wt_lo + base);
#pragma unroll
    for (int q = 0; q < 4; q++) {
        dh[q] = *reinterpret_cast<const uint4*>(hb + q * 8);
        dl[q] = *reinterpret_cast<const uint4*>(lb + q * 8);
    }
}

// ---------------------------------------------------------------------------
// HMMA GEMM. CTA = (g, 128 rows), 8 warps: mw = warp&1 (64 rows),
// nw = warp>>1 (32 cols). Warp tile 64x32, 3 bf16 products, fp32 acc.
// BKC=32, double-buffered, 2 CTAs/SM.
// ---------------------------------------------------------------------------
__global__ __launch_bounds__(256, 2)
void gemm_hmma_kernel(const float* __restrict__ h, float* __restrict__ out) {
    extern __shared__ char smem[];
    const uint32_t sb = smem_u32(smem);
    const int tid  = threadIdx.x;
    const int lane = tid & 31;
    const int warp = tid >> 5;
    const int mw = warp & 1;
    const int nw = warp >> 1;
    const int g  = blockIdx.y;
    const int m0 = blockIdx.x * 128;

    // ---- global load mapping: 2 threads per row, 16 elems each ----
    const int arow = tid >> 1;
    const int half = tid & 1;
    const float* gA = h + ((size_t)(m0 + arow) * G_ + g) * D_ + half * 16;
    const float invh = g_inv_h[(size_t)(m0 + arow) * G_ + g];
    const char* gBh = reinterpret_cast<const char*>(
        g_wt_hi + ((size_t)g * KP + arow) * D_) + half * 32;
    const char* gBl = reinterpret_cast<const char*>(
        g_wt_lo + ((size_t)g * KP + arow) * D_) + half * 32;

    // smem store offset within tile
    const uint32_t srow = arow * LDB + half * 32;

    // ldmatrix base addresses (stage-relative)
    const uint32_t a_lm = (mw * 64 + (lane & 15)) * LDB + (lane >> 4) * 16;
    const uint32_t b_lm = (nw * 32 + (lane & 7) + ((lane >> 4) & 1) * 8) * LDB
                        + ((lane >> 3) & 1) * 16;

    float acc[4][4][4];   // [mt][nf][reg]
#pragma unroll
    for (int mt = 0; mt < 4; mt++)
#pragma unroll
        for (int nf = 0; nf < 4; nf++)
#pragma unroll
            for (int r = 0; r < 4; r++) acc[mt][nf][r] = 0.f;

    // ---- A convert+store: 16 fp32 -> hi/lo bf16 (32B each) ----
    auto store_A = [&](const float4* av, uint32_t stage) {
        uint32_t uh[8], ul[8];
#pragma unroll
        for (int i = 0; i < 4; i++) {
            float x0 = av[i].x * invh, x1 = av[i].y * invh;
            float x2 = av[i].z * invh, x3 = av[i].w * invh;
            __nv_bfloat162 h0 = __float22bfloat162_rn(make_float2(x0, x1));
            __nv_bfloat162 h1 = __float22bfloat162_rn(make_float2(x2, x3));
            float2 f0 = __bfloat1622float2(h0), f1 = __bfloat1622float2(h1);
            __nv_bfloat162 l0 = __float22bfloat162_rn(make_float2(x0 - f0.x, x1 - f0.y));
            __nv_bfloat162 l1 = __float22bfloat162_rn(make_float2(x2 - f1.x, x3 - f1.y));
            uh[i * 2]     = *reinterpret_cast<uint32_t*>(&h0);
            uh[i * 2 + 1] = *reinterpret_cast<uint32_t*>(&h1);
            ul[i * 2]     = *reinterpret_cast<uint32_t*>(&l0);
            ul[i * 2 + 1] = *reinterpret_cast<uint32_t*>(&l1);
        }
        asm volatile("st.shared.v4.b32 [%0], {%1,%2,%3,%4};"
            :: "r"(stage + AH_OFF + srow), "r"(uh[0]), "r"(uh[1]), "r"(uh[2]), "r"(uh[3]) : "memory");
        asm volatile("st.shared.v4.b32 [%0], {%1,%2,%3,%4};"
            :: "r"(stage + AH_OFF + srow + 16), "r"(uh[4]), "r"(uh[5]), "r"(uh[6]), "r"(uh[7]) : "memory");
        asm volatile("st.shared.v4.b32 [%0], {%1,%2,%3,%4};"
            :: "r"(stage + AL_OFF + srow), "r"(ul[0]), "r"(ul[1]), "r"(ul[2]), "r"(ul[3]) : "memory");
        asm volatile("st.shared.v4.b32 [%0], {%1,%2,%3,%4};"
            :: "r"(stage + AL_OFF + srow + 16), "r"(ul[4]), "r"(ul[5]), "r"(ul[6]), "r"(ul[7]) : "memory");
    };

    auto cp_B = [&](int c, uint32_t stage) {
        CP16(stage + BH_OFF + srow,      gBh + (size_t)c * 64);
        CP16(stage + BH_OFF + srow + 16, gBh + (size_t)c * 64 + 16);
        CP16(stage + BL_OFF + srow,      gBl + (size_t)c * 64);
        CP16(stage + BL_OFF + srow + 16, gBl + (size_t)c * 64 + 16);
    };

    // ---- prologue: fill stage 0 ----
    {
        float4 av[4];
#pragma unroll
        for (int i = 0; i < 4; i++)
            av[i] = *reinterpret_cast<const float4*>(gA + i * 4);
        cp_B(0, sb);
        CP_COMMIT();
        store_A(av, sb);
        CP_WAIT0();
    }
    __syncthreads();

    for (int c = 0; c < NCHUNK; c++) {
        const uint32_t stage  = sb + (uint32_t)(c & 1) * STAGE_BYTES;
        const uint32_t nstage = sb + (uint32_t)((c + 1) & 1) * STAGE_BYTES;

        // prefetch next chunk (LDG scoreboarded across compute; cp.async for B)
        float4 av[4];
        if (c + 1 < NCHUNK) {
#pragma unroll
            for (int i = 0; i < 4; i++)
                av[i] = *reinterpret_cast<const float4*>(gA + (c + 1) * BKC + i * 4);
            cp_B(c + 1, nstage);
            CP_COMMIT();
        }

        // ---- compute current chunk: 2 k16-steps ----
#pragma unroll
        for (int ks = 0; ks < 2; ks++) {
            const uint32_t ko = ks * 32;
            uint32_t bh[2][4], bl[2][4];
#pragma unroll
            for (int ng = 0; ng < 2; ng++) {
                LDSM4(bh[ng], stage + BH_OFF + b_lm + ng * (16 * LDB) + ko);
                LDSM4(bl[ng], stage + BL_OFF + b_lm + ng * (16 * LDB) + ko);
            }
#pragma unroll
            for (int mt = 0; mt < 4; mt++) {
                uint32_t ah[4], al[4];
                LDSM4(ah, stage + AH_OFF + a_lm + mt * (16 * LDB) + ko);
                LDSM4(al, stage + AL_OFF + a_lm + mt * (16 * LDB) + ko);
#pragma unroll
                for (int nf = 0; nf < 4; nf++)
                    MMA_BF16(acc[mt][nf], ah,
                             bh[nf >> 1][(nf & 1) * 2], bh[nf >> 1][(nf & 1) * 2 + 1]);
#pragma unroll
                for (int nf = 0; nf < 4; nf++)
                    MMA_BF16(acc[mt][nf], ah,
                             bl[nf >> 1][(nf & 1) * 2], bl[nf >> 1][(nf & 1) * 2 + 1]);
#pragma unroll
                for (int nf = 0; nf < 4; nf++)
                    MMA_BF16(acc[mt][nf], al,
                             bh[nf >> 1][(nf & 1) * 2], bh[nf >> 1][(nf & 1) * 2 + 1]);
            }
        }

        if (c + 1 < NCHUNK) {
            store_A(av, nstage);
            CP_WAIT0();
        }
        __syncthreads();
    }

    // ---- epilogue ----
#pragma unroll
    for (int mt = 0; mt < 4; mt++) {
        const int row = m0 + mw * 64 + mt * 16 + (lane >> 2);
#pragma unroll
        for (int nf = 0; nf < 4; nf++) {
            const int col = nw * 32 + nf * 8 + (lane & 3) * 2;
            if (col < K_) {
                float2 v0 = {acc[mt][nf][0], acc[mt][nf][1]};
                float2 v1 = {acc[mt][nf][2], acc[mt][nf][3]};
                *reinterpret_cast<float2*>(out + ((size_t)row * G_ + g) * K_ + col) = v0;
                *reinterpret_cast<float2*>(out + ((size_t)(row + 8) * G_ + g) * K_ + col) = v1;
            }
        }
    }
}

// ---------------------------------------------------------------------------
extern "C" void kernel_launch(void* const* d_in, const int* in_sizes, int n_in,
                              void* d_out, int out_size) {
    const float* h = (const float*)d_in[0];   // [512,100,768]
    const float* w = (const float*)d_in[1];   // [100,768,100]
    float* out = (float*)d_out;               // [512,100,100]
    (void)in_sizes; (void)n_in; (void)out_size;

    const int smem_bytes = 2 * STAGE_BYTES;   // 81920 per CTA -> 2 CTAs/SM
    cudaFuncSetAttribute(gemm_hmma_kernel,
                         cudaFuncAttributeMaxDynamicSharedMemorySize, smem_bytes);

    norm_h_kernel<<<(B_ * G_) / 8, 256>>>(h);
    norm_w_kernel<<<G_, 512>>>(w);
    split_w_kernel<<<dim3(NCHUNK / 2, G_), 256>>>(w);
    dim3 grid(B_ / 128, G_);
    gemm_hmma_kernel<<<grid, 256, smem_bytes>>>(h, out);
}